// round 5
// baseline (speedup 1.0000x reference)
#include <cuda_runtime.h>
#include <cuda_bf16.h>
#include <cstdint>
#include <math.h>

// Shape fixed by reference: N=4096, T=64, D=1024, fp32.
#define Nn 4096
#define Tt 64
#define Dd 1024
#define THREADS 256          // thread tid owns float4 at d-offset 4*tid
#define TILE 8               // t-rows per tile (32 KB contiguous chunk of h[n])
#define TILE_BYTES (TILE * Dd * 4)   // 32768

// smem layout (bytes):
//   [0,16)      mbar[2]
//   [16,2064)   part[8][64]  : part[i*64 + warp*8 + lane]  (2 KB)
//   [2064,2320) scores[64]   : unnormalized scores of current n
//   [2320,2352) ex[8]        : e_i for current tile
//   [2352]      scale_s, [2356] m_s, [2360] inv_s, pad to 2368
//   [2368, 2368+2*32768) double buffers (16B aligned)
#define SMEM_MBAR_OFF  0
#define SMEM_PART_OFF  16
#define SMEM_SCORE_OFF 2064
#define SMEM_EX_OFF    2320
#define SMEM_SCALE_OFF 2352
#define SMEM_M_OFF     2356
#define SMEM_INV_OFF   2360
#define SMEM_BUF_OFF   2368
#define SMEM_BYTES     (SMEM_BUF_OFF + 2 * TILE_BYTES)   // 67904

__device__ __forceinline__ uint32_t smem_u32(const void* p) {
    uint32_t a;
    asm("{ .reg .u64 t; cvta.to.shared.u64 t, %1; cvt.u32.u64 %0, t; }" : "=r"(a) : "l"(p));
    return a;
}
__device__ __forceinline__ void mbar_init(uint32_t mbar, uint32_t count) {
    asm volatile("mbarrier.init.shared.b64 [%0], %1;" :: "r"(mbar), "r"(count) : "memory");
}
__device__ __forceinline__ void mbar_expect_tx(uint32_t mbar, uint32_t bytes) {
    asm volatile("mbarrier.arrive.expect_tx.shared.b64 _, [%0], %1;" :: "r"(mbar), "r"(bytes) : "memory");
}
__device__ __forceinline__ void bulk_copy_g2s(uint32_t dst_smem, const void* src_gmem,
                                              uint32_t bytes, uint32_t mbar) {
    asm volatile(
        "cp.async.bulk.shared::cluster.global.mbarrier::complete_tx::bytes [%0], [%1], %2, [%3];"
        :: "r"(dst_smem), "l"(src_gmem), "r"(bytes), "r"(mbar) : "memory");
}
__device__ __forceinline__ void mbar_wait_parity(uint32_t mbar, uint32_t parity) {
    uint32_t done;
    asm volatile(
        "{\n\t.reg .pred p;\n\t"
        "mbarrier.try_wait.parity.acquire.cta.shared::cta.b64 p, [%1], %2;\n\t"
        "selp.b32 %0, 1, 0, p;\n\t}"
        : "=r"(done) : "r"(mbar), "r"(parity) : "memory");
    if (!done) {
        asm volatile(
            "{\n\t.reg .pred P1;\n\t"
            "WL_%=:\n\t"
            "mbarrier.try_wait.parity.acquire.cta.shared::cta.b64 P1, [%0], %1, 0x989680;\n\t"
            "@P1 bra.uni WD_%=;\n\t"
            "bra.uni WL_%=;\n\t"
            "WD_%=:\n\t}"
            :: "r"(mbar), "r"(parity) : "memory");
    }
}

__global__ __launch_bounds__(THREADS, 3)
void attn_pool_persist(const float* __restrict__ h,
                       const float* __restrict__ w_score,
                       float* __restrict__ out_pooled,
                       float* __restrict__ out_alpha)
{
    extern __shared__ __align__(16) char smem_raw[];
    float* part    = (float*)(smem_raw + SMEM_PART_OFF);
    float* scores  = (float*)(smem_raw + SMEM_SCORE_OFF);
    float* ex      = (float*)(smem_raw + SMEM_EX_OFF);
    float* scale_s = (float*)(smem_raw + SMEM_SCALE_OFF);
    float* m_s     = (float*)(smem_raw + SMEM_M_OFF);
    float* inv_s   = (float*)(smem_raw + SMEM_INV_OFF);
    const uint32_t mbar0 = smem_u32(smem_raw + SMEM_MBAR_OFF);
    const uint32_t mbar1 = mbar0 + 8;
    const uint32_t buf_s = smem_u32(smem_raw + SMEM_BUF_OFF);
    const float4* buf[2] = { (const float4*)(smem_raw + SMEM_BUF_OFF),
                             (const float4*)(smem_raw + SMEM_BUF_OFF + TILE_BYTES) };

    const int tid  = threadIdx.x;
    const int warp = tid >> 5;
    const int lane = tid & 31;
    const int ncta = gridDim.x;
    const int bid  = blockIdx.x;

    const float4 wv = __ldg((const float4*)w_score + tid);

    // number of n rows handled by this CTA; flat tile stream of length n_count*8
    const int n_count = (Nn - bid + ncta - 1) / ncta;
    const int total_f = n_count * 8;
    if (total_f <= 0) return;

    if (tid == 0) {
        mbar_init(mbar0, 1);
        mbar_init(mbar1, 1);
    }
    __syncthreads();

    // flat tile f -> gmem source
    #define SRC_OF(f) ((const char*)h + \
        ((size_t)(bid + ((f) >> 3) * ncta) * (Tt * Dd) + (size_t)((f) & 7) * (TILE * Dd)) * 4)

    if (tid == 0) {
        mbar_expect_tx(mbar0, TILE_BYTES);
        bulk_copy_g2s(buf_s, SRC_OF(0), TILE_BYTES, mbar0);
        if (total_f > 1) {
            mbar_expect_tx(mbar1, TILE_BYTES);
            bulk_copy_g2s(buf_s + TILE_BYTES, SRC_OF(1), TILE_BYTES, mbar1);
        }
    }

    float m = -INFINITY, Z = 0.0f;      // live in warp 0 lanes 0..7
    float4 acc = make_float4(0.f, 0.f, 0.f, 0.f);

    for (int f = 0; f < total_f; f++) {
        const int b        = f & 1;
        const uint32_t mb  = b ? mbar1 : mbar0;
        const uint32_t par = (f >> 1) & 1;
        const float4* bp   = buf[b];

        mbar_wait_parity(mb, par);

        // ---- slab into regs ----
        float4 v[TILE];
        #pragma unroll
        for (int i = 0; i < TILE; i++)
            v[i] = bp[i * 256 + tid];

        // ---- per-thread partial dots + 2-step butterfly (xor16, xor8) ----
        float pd[TILE];
        #pragma unroll
        for (int i = 0; i < TILE; i++)
            pd[i] = v[i].x * wv.x + v[i].y * wv.y + v[i].z * wv.z + v[i].w * wv.w;
        #pragma unroll
        for (int i = 0; i < TILE; i++) {
            pd[i] += __shfl_xor_sync(0xFFFFFFFFu, pd[i], 16);
            pd[i] += __shfl_xor_sync(0xFFFFFFFFu, pd[i], 8);
        }
        if (lane < 8) {
            #pragma unroll
            for (int i = 0; i < TILE; i++)
                part[i * 64 + warp * 8 + lane] = pd[i];
        }
        __syncthreads();   // sync1: part ready, slab in regs

        // refill this buffer as early as possible
        if (tid == 0 && f + 2 < total_f) {
            mbar_expect_tx(mb, TILE_BYTES);
            bulk_copy_g2s(buf_s + b * TILE_BYTES, SRC_OF(f + 2), TILE_BYTES, mb);
        }

        // ---- warp 0 lanes 0..7: scores + online softmax scalars ----
        if (warp == 0 && lane < 8) {
            const float4* p4 = (const float4*)part + lane * 16;
            float s = 0.0f;
            #pragma unroll
            for (int j = 0; j < 16; j++) {
                float4 q = p4[j];
                s += q.x + q.y + q.z + q.w;
            }
            float tm = s;
            tm = fmaxf(tm, __shfl_xor_sync(0xFFu, tm, 4));
            tm = fmaxf(tm, __shfl_xor_sync(0xFFu, tm, 2));
            tm = fmaxf(tm, __shfl_xor_sync(0xFFu, tm, 1));
            float newm = fmaxf(m, tm);
            float sc   = __expf(m - newm);
            float e    = __expf(s - newm);
            float esum = e;
            esum += __shfl_xor_sync(0xFFu, esum, 4);
            esum += __shfl_xor_sync(0xFFu, esum, 2);
            esum += __shfl_xor_sync(0xFFu, esum, 1);
            Z = Z * sc + esum;
            m = newm;
            ex[lane] = e;
            scores[(f & 7) * 8 + lane] = s;
            if (lane == 0) scale_s[0] = sc;
            if ((f & 7) == 7 && lane == 0) {
                m_s[0]   = m;
                inv_s[0] = 1.0f / Z;
            }
        }
        __syncthreads();   // sync2: e/scale (and m/inv on last tile) ready

        // ---- all threads: cheap acc update ----
        const float sc = scale_s[0];
        const float4 e0 = *(const float4*)ex;
        const float4 e1 = *((const float4*)ex + 1);
        float ev[TILE] = { e0.x, e0.y, e0.z, e0.w, e1.x, e1.y, e1.z, e1.w };
        float ax = acc.x * sc, ay = acc.y * sc, az = acc.z * sc, aw = acc.w * sc;
        #pragma unroll
        for (int i = 0; i < TILE; i++) {
            ax = fmaf(ev[i], v[i].x, ax);
            ay = fmaf(ev[i], v[i].y, ay);
            az = fmaf(ev[i], v[i].z, az);
            aw = fmaf(ev[i], v[i].w, aw);
        }
        acc = make_float4(ax, ay, az, aw);

        // ---- finalize n every 8 tiles ----
        if ((f & 7) == 7) {
            const float inv = inv_s[0];
            const int nidx = bid + (f >> 3) * ncta;
            ((float4*)(out_pooled + (size_t)nidx * Dd))[tid] =
                make_float4(acc.x * inv, acc.y * inv, acc.z * inv, acc.w * inv);
            if (tid < Tt) {
                const float mm = m_s[0];
                out_alpha[(size_t)nidx * Tt + tid] = __expf(scores[tid] - mm) * inv;
            }
            acc = make_float4(0.f, 0.f, 0.f, 0.f);
            m = -INFINITY;
            Z = 0.0f;
        }
    }
    #undef SRC_OF
}

extern "C" void kernel_launch(void* const* d_in, const int* in_sizes, int n_in,
                              void* d_out, int out_size)
{
    const float* h       = (const float*)d_in[0];   // [N, T, D] fp32
    const float* w_score = (const float*)d_in[1];   // [D] fp32

    float* out        = (float*)d_out;
    float* out_pooled = out;                        // [N, D]
    float* out_alpha  = out + (size_t)Nn * Dd;      // [N, T]

    int dev = 0, sms = 148;
    cudaGetDevice(&dev);
    cudaDeviceGetAttribute(&sms, cudaDevAttrMultiProcessorCount, dev);
    int grid = sms * 3;                  // persistent: 3 CTAs/SM
    if (grid > Nn) grid = Nn;

    cudaFuncSetAttribute(attn_pool_persist,
                         cudaFuncAttributeMaxDynamicSharedMemorySize, SMEM_BYTES);

    attn_pool_persist<<<grid, THREADS, SMEM_BYTES>>>(h, w_score, out_pooled, out_alpha);
}

// round 6
// speedup vs baseline: 1.0072x; 1.0072x over previous
#include <cuda_runtime.h>
#include <cuda_bf16.h>
#include <cstdint>
#include <math.h>

// Shape fixed by reference: N=4096, T=64, D=1024, fp32.
#define Nn 4096
#define Tt 64
#define Dd 1024
#define THREADS 256      // thread tid owns float4 at d-offset 4*tid
#define TILE 8           // rows per tile; 8 tiles per n

__global__ __launch_bounds__(THREADS, 2)
void attn_pool_prefetch(const float* __restrict__ h,
                        const float* __restrict__ w_score,
                        float* __restrict__ out_pooled,
                        float* __restrict__ out_alpha)
{
    __shared__ float part[Tt][8];   // part[row][warp], persists across a row-n

    const int tid  = threadIdx.x;
    const int warp = tid >> 5;
    const int lane = tid & 31;
    const int bid  = blockIdx.x;
    const int ncta = gridDim.x;

    const float4 wv = __ldg((const float4*)w_score + tid);

    // rows of n handled by this CTA (interleaved: n = bid + k*ncta)
    const int n_count = (bid < Nn) ? ((Nn - 1 - bid) / ncta + 1) : 0;
    const int total_f = n_count * 8;              // flat tile count (multiple of 8)
    if (total_f == 0) return;

    // flat tile f -> float4 base pointer (+tid gives this thread's column slice)
    auto srcof = [&](int f) -> const float4* {
        const int nidx = bid + (f >> 3) * ncta;
        return (const float4*)(h + (size_t)nidx * (Tt * Dd)) + (f & 7) * (TILE * Dd / 4);
    };

    float4 vA[TILE], vB[TILE];
    {
        const float4* p = srcof(0);
        #pragma unroll
        for (int i = 0; i < TILE; i++) vA[i] = p[i * 256 + tid];
    }

    float m = -INFINITY, Z = 0.0f;
    float4 acc = make_float4(0.f, 0.f, 0.f, 0.f);

    auto step = [&](float4 (&cur)[TILE], float4 (&nxt)[TILE], int f) {
        // ---- prefetch tile f+1 FIRST (front-batched LDG.128, in flight all tile) ----
        if (f + 1 < total_f) {
            const float4* p = srcof(f + 1);
            #pragma unroll
            for (int i = 0; i < TILE; i++) nxt[i] = p[i * 256 + tid];
        }

        // ---- per-thread partial dots + full butterfly ----
        float pd[TILE];
        #pragma unroll
        for (int i = 0; i < TILE; i++)
            pd[i] = cur[i].x * wv.x + cur[i].y * wv.y + cur[i].z * wv.z + cur[i].w * wv.w;
        #pragma unroll
        for (int i = 0; i < TILE; i++) {
            #pragma unroll
            for (int off = 16; off > 0; off >>= 1)
                pd[i] += __shfl_xor_sync(0xFFFFFFFFu, pd[i], off);
        }
        if (lane == 0) {
            #pragma unroll
            for (int i = 0; i < TILE; i++)
                part[(f & 7) * TILE + i][warp] = pd[i];
        }
        __syncthreads();   // part rows for this tile ready

        // ---- vectorized score assembly (broadcast LDS.128) ----
        const float4* p4 = (const float4*)part + (f & 7) * 16;   // 8 rows x 8 floats
        float s[TILE];
        #pragma unroll
        for (int i = 0; i < TILE; i++) {
            float4 a = p4[i * 2], b = p4[i * 2 + 1];
            s[i] = (a.x + a.y) + (a.z + a.w) + (b.x + b.y) + (b.z + b.w);
        }

        // ---- redundant online softmax (identical in all threads) ----
        float tmax = s[0];
        #pragma unroll
        for (int i = 1; i < TILE; i++) tmax = fmaxf(tmax, s[i]);
        const float newm = fmaxf(m, tmax);
        const float sc   = __expf(m - newm);
        float e[TILE], esum = 0.0f;
        #pragma unroll
        for (int i = 0; i < TILE; i++) { e[i] = __expf(s[i] - newm); esum += e[i]; }
        Z = Z * sc + esum;
        m = newm;

        float ax = acc.x * sc, ay = acc.y * sc, az = acc.z * sc, aw = acc.w * sc;
        #pragma unroll
        for (int i = 0; i < TILE; i++) {
            ax = fmaf(e[i], cur[i].x, ax);
            ay = fmaf(e[i], cur[i].y, ay);
            az = fmaf(e[i], cur[i].z, az);
            aw = fmaf(e[i], cur[i].w, aw);
        }
        acc = make_float4(ax, ay, az, aw);

        // ---- finalize n every 8 tiles ----
        if ((f & 7) == 7) {
            const float inv  = 1.0f / Z;
            const int   nidx = bid + (f >> 3) * ncta;
            ((float4*)(out_pooled + (size_t)nidx * Dd))[tid] =
                make_float4(acc.x * inv, acc.y * inv, acc.z * inv, acc.w * inv);
            if (tid < Tt) {
                const float4* q = (const float4*)part + tid * 2;
                float4 a = q[0], b = q[1];
                float srow = (a.x + a.y) + (a.z + a.w) + (b.x + b.y) + (b.z + b.w);
                out_alpha[(size_t)nidx * Tt + tid] = __expf(srow - m) * inv;
            }
            acc = make_float4(0.f, 0.f, 0.f, 0.f);
            m = -INFINITY;
            Z = 0.0f;
            __syncthreads();   // protect part before next n overwrites it
        }
    };

    for (int f = 0; f < total_f; f += 2) {
        step(vA, vB, f);
        step(vB, vA, f + 1);     // total_f is a multiple of 8, so f+1 < total_f
    }
}

extern "C" void kernel_launch(void* const* d_in, const int* in_sizes, int n_in,
                              void* d_out, int out_size)
{
    const float* h       = (const float*)d_in[0];   // [N, T, D] fp32
    const float* w_score = (const float*)d_in[1];   // [D] fp32

    float* out        = (float*)d_out;
    float* out_pooled = out;                        // [N, D]
    float* out_alpha  = out + (size_t)Nn * Dd;      // [N, T]

    int dev = 0, sms = 148;
    cudaGetDevice(&dev);
    cudaDeviceGetAttribute(&sms, cudaDevAttrMultiProcessorCount, dev);
    int grid = sms * 2;                 // persistent, 2 CTAs/SM (reg-limited)
    if (grid > Nn) grid = Nn;

    attn_pool_prefetch<<<grid, THREADS>>>(h, w_score, out_pooled, out_alpha);
}